// round 7
// baseline (speedup 1.0000x reference)
#include <cuda_runtime.h>
#include <float.h>

#define BATCH 32
#define HH 1024
#define WW 1024
#define TOPK 200
#define HOT_T 0.9993f
#define STRIPS 8          // 8 strips x 128 cols
#define CPW 128           // columns per warp
#define WPB 4             // warps per block
#define RPB 64            // rows per band
#define NBAND (HH / RPB)  // 16
#define SEGS_PER_IMG (STRIPS * NBAND)   // 128
#define LANECAP 32        // slots per lane sub-segment
#define HOTCAP 24
#define COLDCAP 8
#define SUBS_PER_IMG (SEGS_PER_IMG * 32)   // 4096 lane sub-segments

// static device scratch — per-LANE private sub-segments (hot front, cold back)
__device__ unsigned long long d_seg[BATCH * SUBS_PER_IMG * LANECAP];  // 32 MB
__device__ unsigned int d_subcnt[BATCH * SUBS_PER_IMG];               // hot | cold<<16

__device__ __forceinline__ float4 mk4(float x) { return make_float4(x, x, x, x); }

__device__ __forceinline__ void emit_peak(float val, unsigned idx,
                                          unsigned long long* lseg,
                                          int& nh, int& nc) {
    unsigned long long key =
        ((unsigned long long)__float_as_uint(val) << 32) |
        (unsigned long long)(0xFFFFFFFFu - idx);
    if (val > HOT_T) {
        if (nh < HOTCAP) lseg[nh] = key;
        nh++;
    } else {
        if (nc < COLDCAP) lseg[LANECAP - 1 - nc] = key;
        nc++;
    }
}

// Barrier-free, atomic-free, ballot-free float4 7x7 max-pool NMS.
// Warp owns 128 cols x 64 rows; lane owns 4 columns + private output sub-segment.
template <bool CHECKED>
__global__ void __launch_bounds__(128) nms_kernel(const float* __restrict__ in) {
    const int img = blockIdx.z;
    const int wid = threadIdx.x >> 5;
    const int lane = threadIdx.x & 31;
    const int strip = blockIdx.x * WPB + wid;       // 0..7
    const int band = CHECKED ? (blockIdx.y ? NBAND - 1 : 0) : (1 + blockIdx.y);
    const int out0 = strip * CPW;
    const int colbase = out0 + 4 * lane;
    const int ry0 = band * RPB;
    const float* base = in + (size_t)img * HH * WW;

    const int subid = ((img * NBAND + band) * STRIPS + strip) * 32 + lane;
    unsigned long long* lseg = d_seg + (size_t)subid * LANECAP;
    int nhot = 0, ncold = 0;

    const bool haloLane = (lane == 0) || (lane == 31);
    const int hcol = (lane == 0) ? (out0 - 4) : (out0 + CPW);
    const bool haloOK = haloLane && ((unsigned)hcol < WW);

    // rolling vertical state: h[r-1..r-3], m3 centered r-2..r-5, v[r-1..r-3]
    float4 hp0 = mk4(-FLT_MAX), hp1 = hp0, hp2 = hp0;
    float4 m30 = hp0, m31 = hp0, m32 = hp0, m33 = hp0;
    float4 cv0 = hp0, cv1 = hp0, cv2 = hp0;

    #pragma unroll 2
    for (int g = 0; g < 18; ++g) {               // rows ry0-3 .. ry0+68
        const int rb = ry0 - 3 + g * 4;
        float4 v[4], q[4];
        #pragma unroll
        for (int k = 0; k < 4; k++) {
            int r = rb + k;
            if (CHECKED) {
                bool rOK = ((unsigned)r < HH);
                v[k] = mk4(-FLT_MAX);
                q[k] = mk4(-FLT_MAX);
                if (rOK)
                    v[k] = *reinterpret_cast<const float4*>(base + (size_t)r * WW + colbase);
                if (rOK && haloOK)
                    q[k] = *reinterpret_cast<const float4*>(base + (size_t)r * WW + hcol);
            } else {
                v[k] = *reinterpret_cast<const float4*>(base + (size_t)r * WW + colbase);
                q[k] = haloOK
                    ? *reinterpret_cast<const float4*>(base + (size_t)r * WW + hcol)
                    : mk4(-FLT_MAX);
            }
        }
        #pragma unroll
        for (int k = 0; k < 4; k++) {
            const int r = rb + k;
            float4 vv = v[k], qq = q[k];
            // own-quad prefix/suffix maxes
            float p1 = fmaxf(vv.x, vv.y);
            float p2 = fmaxf(p1, vv.z);
            float p3 = fmaxf(p2, vv.w);
            float s2 = fmaxf(vv.z, vv.w);
            float s1 = fmaxf(vv.y, s2);
            // halo-quad values (meaningful on lanes 0 / 31 only)
            float qs2 = fmaxf(qq.z, qq.w);
            float qs1 = fmaxf(qq.y, qs2);
            float qp1 = fmaxf(qq.x, qq.y);
            float qp2 = fmaxf(qp1, qq.z);

            float ls1 = __shfl_up_sync(0xffffffffu, s1, 1);
            float ls2 = __shfl_up_sync(0xffffffffu, s2, 1);
            float ls3 = __shfl_up_sync(0xffffffffu, vv.w, 1);
            float rp0 = __shfl_down_sync(0xffffffffu, vv.x, 1);
            float rp1 = __shfl_down_sync(0xffffffffu, p1, 1);
            float rp2 = __shfl_down_sync(0xffffffffu, p2, 1);
            if (lane == 0)  { ls1 = qs1;  ls2 = qs2;  ls3 = qq.w; }
            if (lane == 31) { rp0 = qq.x; rp1 = qp1;  rp2 = qp2;  }

            // horizontal 7-max
            float4 h;
            h.x = fmaxf(ls1, p3);
            h.y = fmaxf(fmaxf(ls2, rp0), p3);
            h.z = fmaxf(fmaxf(ls3, rp1), p3);
            h.w = fmaxf(rp2, p3);

            // vertical cascade
            float4 m3n, pooled;
            m3n.x = fmaxf(fmaxf(hp1.x, hp0.x), h.x);
            m3n.y = fmaxf(fmaxf(hp1.y, hp0.y), h.y);
            m3n.z = fmaxf(fmaxf(hp1.z, hp0.z), h.z);
            m3n.w = fmaxf(fmaxf(hp1.w, hp0.w), h.w);
            pooled.x = fmaxf(fmaxf(m33.x, hp2.x), m3n.x);
            pooled.y = fmaxf(fmaxf(m33.y, hp2.y), m3n.y);
            pooled.z = fmaxf(fmaxf(m33.z, hp2.z), m3n.z);
            pooled.w = fmaxf(fmaxf(m33.w, hp2.w), m3n.w);

            // emission: per-lane private, no warp coordination
            if (r >= ry0 + 3 && r <= ry0 + RPB + 2) {
                const unsigned orow = (unsigned)(r - 3) * WW;
                if ((cv2.x > 0.1f) && (pooled.x == cv2.x))
                    emit_peak(cv2.x, orow + colbase + 0, lseg, nhot, ncold);
                if ((cv2.y > 0.1f) && (pooled.y == cv2.y))
                    emit_peak(cv2.y, orow + colbase + 1, lseg, nhot, ncold);
                if ((cv2.z > 0.1f) && (pooled.z == cv2.z))
                    emit_peak(cv2.z, orow + colbase + 2, lseg, nhot, ncold);
                if ((cv2.w > 0.1f) && (pooled.w == cv2.w))
                    emit_peak(cv2.w, orow + colbase + 3, lseg, nhot, ncold);
            }
            m33 = m32; m32 = m31; m31 = m30; m30 = m3n;
            hp2 = hp1; hp1 = hp0; hp0 = h;
            cv2 = cv1; cv1 = cv0; cv0 = vv;
        }
    }
    unsigned nh = nhot > HOTCAP ? HOTCAP : (unsigned)nhot;
    unsigned ncl = ncold > COLDCAP ? COLDCAP : (unsigned)ncold;
    d_subcnt[subid] = nh | (ncl << 16);
}

// One block per image. Gather hot keys from per-lane sub-segments,
// hybrid register/shared bitonic sort, emit top-200.
__global__ void __launch_bounds__(1024) topk_kernel(float* __restrict__ out) {
    const int img = blockIdx.x;
    const int tid = threadIdx.x;

    __shared__ unsigned long long buf[1024];
    __shared__ int s_cnt;
    __shared__ unsigned hist[256];
    __shared__ unsigned s_above, s_digit, s_total;

    const int cb = img * SUBS_PER_IMG;
    if (tid == 0) s_cnt = 0;
    __syncthreads();

    // gather hot keys: thread handles 4 sub-segments
    #pragma unroll
    for (int ss = 0; ss < SUBS_PER_IMG; ss += 1024) {
        int s = ss + tid;
        unsigned c = d_subcnt[cb + s];
        int hot = (int)(c & 0xffffu);
        const unsigned long long* lseg = d_seg + (size_t)(cb + s) * LANECAP;
        for (int i = 0; i < hot; i++) {
            unsigned long long k = lseg[i];
            int pos = atomicAdd(&s_cnt, 1);
            if (pos < 1024) buf[pos] = k;
        }
    }
    __syncthreads();
    int nhot = s_cnt;

    if (nhot >= TOPK && nhot <= 1024) {
        if (tid >= nhot) buf[tid] = 0ull;
    } else {
        // ---- fallback: radix-select over all hot+cold entries ----
        const int NFLAT = SUBS_PER_IMG * LANECAP;   // 131072
        unsigned prefix = 0, above = 0;
        int shift = 24;
        bool done = false;
        for (int lev = 0; lev < 4 && !done; lev++) {
            shift = 24 - lev * 8;
            for (int i = tid; i < 256; i += 1024) hist[i] = 0;
            __syncthreads();
            for (int i = tid; i < NFLAT; i += 1024) {
                int s = i >> 5, slot = i & (LANECAP - 1);
                unsigned c = d_subcnt[cb + s];
                int h = (int)(c & 0xffffu), cl = (int)(c >> 16);
                if (slot < h || slot >= LANECAP - cl) {
                    unsigned vb = (unsigned)(d_seg[(size_t)(cb + s) * LANECAP + slot] >> 32);
                    if (lev == 0 || (vb >> (shift + 8)) == prefix)
                        atomicAdd(&hist[(vb >> shift) & 0xFFu], 1u);
                }
            }
            __syncthreads();
            if (tid == 0) {
                unsigned cum = 0; int dsel = 0;
                for (int b = 255; b >= 0; b--) {
                    if (above + cum + hist[b] >= TOPK || b == 0) { dsel = b; break; }
                    cum += hist[b];
                }
                s_above = above + cum;
                s_digit = (unsigned)dsel;
                s_total = above + cum + hist[dsel];
            }
            __syncthreads();
            above = s_above;
            prefix = (prefix << 8) | s_digit;
            done = (s_total <= 1024);
            __syncthreads();
        }
        if (tid == 0) s_cnt = 0;
        __syncthreads();
        for (int i = tid; i < NFLAT; i += 1024) {
            int s = i >> 5, slot = i & (LANECAP - 1);
            unsigned c = d_subcnt[cb + s];
            int h = (int)(c & 0xffffu), cl = (int)(c >> 16);
            if (slot < h || slot >= LANECAP - cl) {
                unsigned long long k = d_seg[(size_t)(cb + s) * LANECAP + slot];
                if (((unsigned)(k >> 32) >> shift) >= prefix) {
                    int pos = atomicAdd(&s_cnt, 1);
                    if (pos < 1024) buf[pos] = k;
                }
            }
        }
        __syncthreads();
        int m = s_cnt < 1024 ? s_cnt : 1024;
        if (tid >= m) buf[tid] = 0ull;
    }
    __syncthreads();

    // hybrid bitonic sort, descending: j>=32 via shared, j<32 via shfl_xor
    unsigned long long key = buf[tid];
    #pragma unroll
    for (int k = 2; k <= 1024; k <<= 1) {
        #pragma unroll
        for (int j = k >> 1; j >= 32; j >>= 1) {
            buf[tid] = key;
            __syncthreads();
            unsigned long long other = buf[tid ^ j];
            __syncthreads();
            bool takeMax = (((tid & k) == 0) == ((tid & j) == 0));
            key = (takeMax == (key > other)) ? key : other;
        }
        #pragma unroll
        for (int j = (k >> 1) < 16 ? (k >> 1) : 16; j >= 1; j >>= 1) {
            unsigned long long other = __shfl_xor_sync(0xffffffffu, key, j);
            bool takeMax = (((tid & k) == 0) == ((tid & j) == 0));
            key = (takeMax == (key > other)) ? key : other;
        }
    }

    // emit: coords [B, K, 2] (row, col) then probs [B, K], all fp32
    float* coords = out;
    float* probs = out + (size_t)BATCH * TOPK * 2;
    if (tid < TOPK) {
        float prob; unsigned row, col;
        if (key == 0ull) {
            prob = 0.0f; row = 0; col = 0;
        } else {
            prob = __uint_as_float((unsigned)(key >> 32));
            unsigned idx = 0xFFFFFFFFu - (unsigned)(key & 0xFFFFFFFFull);
            row = idx / WW; col = idx % WW;
        }
        size_t o = (size_t)img * TOPK + tid;
        coords[o * 2 + 0] = (float)row;
        coords[o * 2 + 1] = (float)col;
        probs[o] = prob;
    }
}

extern "C" void kernel_launch(void* const* d_in, const int* in_sizes, int n_in,
                              void* d_out, int out_size) {
    const float* in = (const float*)d_in[0];
    float* out = (float*)d_out;

    dim3 gi(STRIPS / WPB, NBAND - 2, BATCH);   // interior bands 1..14 (unchecked)
    dim3 ge(STRIPS / WPB, 2, BATCH);           // edge bands 0 and 15 (checked)
    nms_kernel<false><<<gi, 128>>>(in);
    nms_kernel<true><<<ge, 128>>>(in);
    topk_kernel<<<BATCH, 1024>>>(out);
}

// round 8
// speedup vs baseline: 1.0509x; 1.0509x over previous
#include <cuda_runtime.h>
#include <float.h>

#define BATCH 32
#define HH 1024
#define WW 1024
#define TOPK 200
#define HOT_T 0.9993f
#define STRIPS 8          // 8 strips x 128 cols
#define CPW 128           // columns per warp
#define WPB 4             // warps per block
#define RPB 64            // rows per band
#define NBAND (HH / RPB)  // 16
#define SEGS_PER_IMG (STRIPS * NBAND)   // 128
#define LANECAP 32        // slots per lane sub-segment (max peaks/region is 18)
#define HOTCAP 24
#define COLDCAP 8
#define SUBS_PER_IMG (SEGS_PER_IMG * 32)   // 4096 lane sub-segments

// static device scratch — per-LANE private sub-segments (hot front, cold back)
__device__ unsigned long long d_seg[BATCH * SUBS_PER_IMG * LANECAP];  // 32 MB
__device__ unsigned int d_subcnt[BATCH * SUBS_PER_IMG];               // hot | cold<<16

__device__ __forceinline__ float4 mk4(float x) { return make_float4(x, x, x, x); }

__device__ __forceinline__ void emit_peak(float val, unsigned idx,
                                          unsigned long long* lseg,
                                          int& nh, int& nc) {
    unsigned long long key =
        ((unsigned long long)__float_as_uint(val) << 32) |
        (unsigned long long)(0xFFFFFFFFu - idx);
    if (val > HOT_T) {
        if (nh < HOTCAP) lseg[nh] = key;
        nh++;
    } else {
        if (nc < COLDCAP) lseg[LANECAP - 1 - nc] = key;
        nc++;
    }
}

// Single-kernel, barrier/atomic/ballot-free float4 7x7 max-pool NMS.
// Bounds handled by CLAMPED addressing: a clamped out-of-range row/col maps to
// a cell already inside the max window, so pooled is exact. Warp = 128 cols x
// 64 rows; lane owns 4 cols + a private output sub-segment.
__global__ void __launch_bounds__(128, 7) nms_kernel(const float* __restrict__ in) {
    const int img = blockIdx.z;
    const int wid = threadIdx.x >> 5;
    const int lane = threadIdx.x & 31;
    const int strip = blockIdx.x * WPB + wid;       // 0..7
    const int band = blockIdx.y;                    // 0..15
    const int out0 = strip * CPW;
    const int colbase = out0 + 4 * lane;
    const int ry0 = band * RPB;
    const float* base = in + (size_t)img * HH * WW;

    const int subid = ((img * NBAND + band) * STRIPS + strip) * 32 + lane;
    unsigned long long* lseg = d_seg + (size_t)subid * LANECAP;
    int nhot = 0, ncold = 0;

    const bool haloLane = (lane == 0) || (lane == 31);
    int hcol = (lane == 0) ? (out0 - 4) : (out0 + CPW);
    hcol = min(max(hcol, 0), WW - 4);               // clamped: exact (see header)

    // rolling vertical state: h[r-1..r-3], m3 centered r-2..r-5, v[r-1..r-3]
    float4 hp0 = mk4(-FLT_MAX), hp1 = hp0, hp2 = hp0;
    float4 m30 = hp0, m31 = hp0, m32 = hp0, m33 = hp0;
    float4 cv0 = hp0, cv1 = hp0, cv2 = hp0;

    for (int g = 0; g < 18; ++g) {                  // rows ry0-3 .. ry0+68
        const int rb = ry0 - 3 + g * 4;
        float4 v[4];
        float qa[4], qb[4], qc[4];                  // reduced halo scalars
        #pragma unroll
        for (int k = 0; k < 4; k++) {
            int rc = min(max(rb + k, 0), HH - 1);   // clamped row: exact
            v[k] = *reinterpret_cast<const float4*>(base + (size_t)rc * WW + colbase);
            float4 qq = mk4(-FLT_MAX);
            if (haloLane)
                qq = *reinterpret_cast<const float4*>(base + (size_t)rc * WW + hcol);
            // lane 0 needs suffix maxes of left quad; lane 31 prefix of right quad
            qa[k] = (lane == 0) ? fmaxf(qq.y, fmaxf(qq.z, qq.w)) : qq.x;
            qb[k] = (lane == 0) ? fmaxf(qq.z, qq.w) : fmaxf(qq.x, qq.y);
            qc[k] = (lane == 0) ? qq.w : fmaxf(fmaxf(qq.x, qq.y), qq.z);
        }
        #pragma unroll
        for (int k = 0; k < 4; k++) {
            const int r = rb + k;
            float4 vv = v[k];
            // own-quad prefix/suffix maxes
            float p1 = fmaxf(vv.x, vv.y);
            float p2 = fmaxf(p1, vv.z);
            float p3 = fmaxf(p2, vv.w);
            float s2 = fmaxf(vv.z, vv.w);
            float s1 = fmaxf(vv.y, s2);

            float ls1 = __shfl_up_sync(0xffffffffu, s1, 1);
            float ls2 = __shfl_up_sync(0xffffffffu, s2, 1);
            float ls3 = __shfl_up_sync(0xffffffffu, vv.w, 1);
            float rp0 = __shfl_down_sync(0xffffffffu, vv.x, 1);
            float rp1 = __shfl_down_sync(0xffffffffu, p1, 1);
            float rp2 = __shfl_down_sync(0xffffffffu, p2, 1);
            if (lane == 0)  { ls1 = qa[k]; ls2 = qb[k]; ls3 = qc[k]; }
            if (lane == 31) { rp0 = qa[k]; rp1 = qb[k]; rp2 = qc[k]; }

            // horizontal 7-max
            float4 h;
            h.x = fmaxf(ls1, p3);
            h.y = fmaxf(fmaxf(ls2, rp0), p3);
            h.z = fmaxf(fmaxf(ls3, rp1), p3);
            h.w = fmaxf(rp2, p3);

            // vertical cascade
            float4 m3n, pooled;
            m3n.x = fmaxf(fmaxf(hp1.x, hp0.x), h.x);
            m3n.y = fmaxf(fmaxf(hp1.y, hp0.y), h.y);
            m3n.z = fmaxf(fmaxf(hp1.z, hp0.z), h.z);
            m3n.w = fmaxf(fmaxf(hp1.w, hp0.w), h.w);
            pooled.x = fmaxf(fmaxf(m33.x, hp2.x), m3n.x);
            pooled.y = fmaxf(fmaxf(m33.y, hp2.y), m3n.y);
            pooled.z = fmaxf(fmaxf(m33.z, hp2.z), m3n.z);
            pooled.w = fmaxf(fmaxf(m33.w, hp2.w), m3n.w);

            // emission: per-lane private, no warp coordination
            if (r >= ry0 + 3 && r <= ry0 + RPB + 2) {
                const unsigned orow = (unsigned)(r - 3) * WW;
                if ((cv2.x > 0.1f) && (pooled.x == cv2.x))
                    emit_peak(cv2.x, orow + colbase + 0, lseg, nhot, ncold);
                if ((cv2.y > 0.1f) && (pooled.y == cv2.y))
                    emit_peak(cv2.y, orow + colbase + 1, lseg, nhot, ncold);
                if ((cv2.z > 0.1f) && (pooled.z == cv2.z))
                    emit_peak(cv2.z, orow + colbase + 2, lseg, nhot, ncold);
                if ((cv2.w > 0.1f) && (pooled.w == cv2.w))
                    emit_peak(cv2.w, orow + colbase + 3, lseg, nhot, ncold);
            }
            m33 = m32; m32 = m31; m31 = m30; m30 = m3n;
            hp2 = hp1; hp1 = hp0; hp0 = h;
            cv2 = cv1; cv1 = cv0; cv0 = vv;
        }
    }
    unsigned nh = nhot > HOTCAP ? HOTCAP : (unsigned)nhot;
    unsigned ncl = ncold > COLDCAP ? COLDCAP : (unsigned)ncold;
    d_subcnt[subid] = nh | (ncl << 16);
}

// One block per image. Gather hot keys from per-lane sub-segments,
// hybrid register/shared bitonic sort, emit top-200.
__global__ void __launch_bounds__(1024) topk_kernel(float* __restrict__ out) {
    const int img = blockIdx.x;
    const int tid = threadIdx.x;

    __shared__ unsigned long long buf[1024];
    __shared__ int s_cnt;
    __shared__ unsigned hist[256];
    __shared__ unsigned s_above, s_digit, s_total;

    const int cb = img * SUBS_PER_IMG;
    if (tid == 0) s_cnt = 0;
    __syncthreads();

    // gather hot keys: thread handles 4 sub-segments
    #pragma unroll
    for (int ss = 0; ss < SUBS_PER_IMG; ss += 1024) {
        int s = ss + tid;
        unsigned c = d_subcnt[cb + s];
        int hot = (int)(c & 0xffffu);
        const unsigned long long* lseg = d_seg + (size_t)(cb + s) * LANECAP;
        for (int i = 0; i < hot; i++) {
            unsigned long long k = lseg[i];
            int pos = atomicAdd(&s_cnt, 1);
            if (pos < 1024) buf[pos] = k;
        }
    }
    __syncthreads();
    int nhot = s_cnt;

    if (nhot >= TOPK && nhot <= 1024) {
        if (tid >= nhot) buf[tid] = 0ull;
    } else {
        // ---- fallback: radix-select over all hot+cold entries ----
        const int NFLAT = SUBS_PER_IMG * LANECAP;   // 131072
        unsigned prefix = 0, above = 0;
        int shift = 24;
        bool done = false;
        for (int lev = 0; lev < 4 && !done; lev++) {
            shift = 24 - lev * 8;
            for (int i = tid; i < 256; i += 1024) hist[i] = 0;
            __syncthreads();
            for (int i = tid; i < NFLAT; i += 1024) {
                int s = i >> 5, slot = i & (LANECAP - 1);
                unsigned c = d_subcnt[cb + s];
                int h = (int)(c & 0xffffu), cl = (int)(c >> 16);
                if (slot < h || slot >= LANECAP - cl) {
                    unsigned vb = (unsigned)(d_seg[(size_t)(cb + s) * LANECAP + slot] >> 32);
                    if (lev == 0 || (vb >> (shift + 8)) == prefix)
                        atomicAdd(&hist[(vb >> shift) & 0xFFu], 1u);
                }
            }
            __syncthreads();
            if (tid == 0) {
                unsigned cum = 0; int dsel = 0;
                for (int b = 255; b >= 0; b--) {
                    if (above + cum + hist[b] >= TOPK || b == 0) { dsel = b; break; }
                    cum += hist[b];
                }
                s_above = above + cum;
                s_digit = (unsigned)dsel;
                s_total = above + cum + hist[dsel];
            }
            __syncthreads();
            above = s_above;
            prefix = (prefix << 8) | s_digit;
            done = (s_total <= 1024);
            __syncthreads();
        }
        if (tid == 0) s_cnt = 0;
        __syncthreads();
        for (int i = tid; i < NFLAT; i += 1024) {
            int s = i >> 5, slot = i & (LANECAP - 1);
            unsigned c = d_subcnt[cb + s];
            int h = (int)(c & 0xffffu), cl = (int)(c >> 16);
            if (slot < h || slot >= LANECAP - cl) {
                unsigned long long k = d_seg[(size_t)(cb + s) * LANECAP + slot];
                if (((unsigned)(k >> 32) >> shift) >= prefix) {
                    int pos = atomicAdd(&s_cnt, 1);
                    if (pos < 1024) buf[pos] = k;
                }
            }
        }
        __syncthreads();
        int m = s_cnt < 1024 ? s_cnt : 1024;
        if (tid >= m) buf[tid] = 0ull;
    }
    __syncthreads();

    // hybrid bitonic sort, descending: j>=32 via shared, j<32 via shfl_xor
    unsigned long long key = buf[tid];
    #pragma unroll
    for (int k = 2; k <= 1024; k <<= 1) {
        #pragma unroll
        for (int j = k >> 1; j >= 32; j >>= 1) {
            buf[tid] = key;
            __syncthreads();
            unsigned long long other = buf[tid ^ j];
            __syncthreads();
            bool takeMax = (((tid & k) == 0) == ((tid & j) == 0));
            key = (takeMax == (key > other)) ? key : other;
        }
        #pragma unroll
        for (int j = (k >> 1) < 16 ? (k >> 1) : 16; j >= 1; j >>= 1) {
            unsigned long long other = __shfl_xor_sync(0xffffffffu, key, j);
            bool takeMax = (((tid & k) == 0) == ((tid & j) == 0));
            key = (takeMax == (key > other)) ? key : other;
        }
    }

    // emit: coords [B, K, 2] (row, col) then probs [B, K], all fp32
    float* coords = out;
    float* probs = out + (size_t)BATCH * TOPK * 2;
    if (tid < TOPK) {
        float prob; unsigned row, col;
        if (key == 0ull) {
            prob = 0.0f; row = 0; col = 0;
        } else {
            prob = __uint_as_float((unsigned)(key >> 32));
            unsigned idx = 0xFFFFFFFFu - (unsigned)(key & 0xFFFFFFFFull);
            row = idx / WW; col = idx % WW;
        }
        size_t o = (size_t)img * TOPK + tid;
        coords[o * 2 + 0] = (float)row;
        coords[o * 2 + 1] = (float)col;
        probs[o] = prob;
    }
}

extern "C" void kernel_launch(void* const* d_in, const int* in_sizes, int n_in,
                              void* d_out, int out_size) {
    const float* in = (const float*)d_in[0];
    float* out = (float*)d_out;

    dim3 grid(STRIPS / WPB, NBAND, BATCH);   // 2 x 16 x 32 = 1024 blocks
    nms_kernel<<<grid, 128>>>(in);
    topk_kernel<<<BATCH, 1024>>>(out);
}